// round 2
// baseline (speedup 1.0000x reference)
#include <cuda_runtime.h>

#define B_  4
#define L_  2048
#define D_  512
#define DK_ 256

// Scratch (allocation-free per harness rules)
__device__ float g_Q[B_ * L_ * DK_];                 //  8 MB
__device__ float g_K[B_ * L_ * DK_];                 //  8 MB
__device__ float g_V[B_ * L_ * D_];                  // 16 MB
__device__ float g_QE[(size_t)B_ * L_ * L_];         // 67 MB
__device__ float g_S[(size_t)B_ * L_ * L_];          // 67 MB

// ---------------------------------------------------------------------------
// Classic 128x128x16 SIMT SGEMM, 256 threads, 8x8 register tile.
// C[M,N] = A[M,K] * B[K,N], all row-major. Batched via blockIdx.z + strides.
// All problem dims divide tiles exactly (checked on host side), no predication.
// ---------------------------------------------------------------------------
__global__ __launch_bounds__(256, 2)
void sgemm_nn(const float* __restrict__ A, const float* __restrict__ Bm,
              float* __restrict__ C, int M, int N, int Kd,
              long long sA, long long sB, long long sC)
{
    __shared__ float As[16][132];   // [k][m], padded to reduce bank conflicts
    __shared__ float Bs[16][132];   // [k][n]

    const int bz = blockIdx.z;
    A  += (size_t)bz * sA;
    Bm += (size_t)bz * sB;
    C  += (size_t)bz * sC;

    const int bm = blockIdx.y * 128;
    const int bn = blockIdx.x * 128;
    const int tid = threadIdx.x;

    const int arow  = tid >> 2;           // 0..63
    const int acol4 = (tid & 3) << 2;     // 0,4,8,12
    const int brow  = tid >> 5;           // 0..7
    const int bcol4 = (tid & 31) << 2;    // 0..124
    const int ty = tid >> 4;              // 0..15
    const int tx = tid & 15;              // 0..15

    float acc[8][8];
#pragma unroll
    for (int i = 0; i < 8; i++)
#pragma unroll
        for (int j = 0; j < 8; j++) acc[i][j] = 0.f;

    for (int k0 = 0; k0 < Kd; k0 += 16) {
#pragma unroll
        for (int i = 0; i < 2; i++) {
            int r = arow + i * 64;
            float4 v = *reinterpret_cast<const float4*>(
                A + (size_t)(bm + r) * Kd + k0 + acol4);
            As[acol4 + 0][r] = v.x;
            As[acol4 + 1][r] = v.y;
            As[acol4 + 2][r] = v.z;
            As[acol4 + 3][r] = v.w;
        }
#pragma unroll
        for (int i = 0; i < 2; i++) {
            int r = brow + i * 8;
            *reinterpret_cast<float4*>(&Bs[r][bcol4]) =
                *reinterpret_cast<const float4*>(
                    Bm + (size_t)(k0 + r) * N + bn + bcol4);
        }
        __syncthreads();

#pragma unroll
        for (int k = 0; k < 16; k++) {
            float4 a0 = *reinterpret_cast<const float4*>(&As[k][ty * 8]);
            float4 a1 = *reinterpret_cast<const float4*>(&As[k][ty * 8 + 4]);
            float4 b0 = *reinterpret_cast<const float4*>(&Bs[k][tx * 8]);
            float4 b1 = *reinterpret_cast<const float4*>(&Bs[k][tx * 8 + 4]);
            float ra[8] = {a0.x, a0.y, a0.z, a0.w, a1.x, a1.y, a1.z, a1.w};
            float rb[8] = {b0.x, b0.y, b0.z, b0.w, b1.x, b1.y, b1.z, b1.w};
#pragma unroll
            for (int i = 0; i < 8; i++)
#pragma unroll
                for (int j = 0; j < 8; j++)
                    acc[i][j] = fmaf(ra[i], rb[j], acc[i][j]);
        }
        __syncthreads();
    }

#pragma unroll
    for (int i = 0; i < 8; i++) {
        float* cp = C + (size_t)(bm + ty * 8 + i) * N + bn + tx * 8;
        *reinterpret_cast<float4*>(cp)     = make_float4(acc[i][0], acc[i][1], acc[i][2], acc[i][3]);
        *reinterpret_cast<float4*>(cp + 4) = make_float4(acc[i][4], acc[i][5], acc[i][6], acc[i][7]);
    }
}

// ---------------------------------------------------------------------------
// NT variant: C[M,N] = A[M,K] * B[N,K]^T (both operands row-major along K).
// SKEW=false : plain store (used for QE = Q * E^T)
// SKEW=true  : S = (QK^T + skew(QE)) / sqrt(256), gathering QE in the epilogue
// ---------------------------------------------------------------------------
template <bool SKEW>
__global__ __launch_bounds__(256, 2)
void sgemm_nt(const float* __restrict__ A, const float* __restrict__ Bm,
              float* __restrict__ C, int M, int N, int Kd,
              long long sA, long long sB, long long sC,
              const float* __restrict__ QE)
{
    __shared__ float As[16][132];
    __shared__ float Bs[16][132];

    const int bz = blockIdx.z;
    A  += (size_t)bz * sA;
    Bm += (size_t)bz * sB;
    C  += (size_t)bz * sC;

    const int bm = blockIdx.y * 128;
    const int bn = blockIdx.x * 128;
    const int tid = threadIdx.x;

    const int arow  = tid >> 2;
    const int acol4 = (tid & 3) << 2;
    const int ty = tid >> 4;
    const int tx = tid & 15;

    float acc[8][8];
#pragma unroll
    for (int i = 0; i < 8; i++)
#pragma unroll
        for (int j = 0; j < 8; j++) acc[i][j] = 0.f;

    for (int k0 = 0; k0 < Kd; k0 += 16) {
#pragma unroll
        for (int i = 0; i < 2; i++) {
            int r = arow + i * 64;
            float4 v = *reinterpret_cast<const float4*>(
                A + (size_t)(bm + r) * Kd + k0 + acol4);
            As[acol4 + 0][r] = v.x;
            As[acol4 + 1][r] = v.y;
            As[acol4 + 2][r] = v.z;
            As[acol4 + 3][r] = v.w;
        }
#pragma unroll
        for (int i = 0; i < 2; i++) {
            int r = arow + i * 64;
            float4 v = *reinterpret_cast<const float4*>(
                Bm + (size_t)(bn + r) * Kd + k0 + acol4);
            Bs[acol4 + 0][r] = v.x;
            Bs[acol4 + 1][r] = v.y;
            Bs[acol4 + 2][r] = v.z;
            Bs[acol4 + 3][r] = v.w;
        }
        __syncthreads();

#pragma unroll
        for (int k = 0; k < 16; k++) {
            float4 a0 = *reinterpret_cast<const float4*>(&As[k][ty * 8]);
            float4 a1 = *reinterpret_cast<const float4*>(&As[k][ty * 8 + 4]);
            float4 b0 = *reinterpret_cast<const float4*>(&Bs[k][tx * 8]);
            float4 b1 = *reinterpret_cast<const float4*>(&Bs[k][tx * 8 + 4]);
            float ra[8] = {a0.x, a0.y, a0.z, a0.w, a1.x, a1.y, a1.z, a1.w};
            float rb[8] = {b0.x, b0.y, b0.z, b0.w, b1.x, b1.y, b1.z, b1.w};
#pragma unroll
            for (int i = 0; i < 8; i++)
#pragma unroll
                for (int j = 0; j < 8; j++)
                    acc[i][j] = fmaf(ra[i], rb[j], acc[i][j]);
        }
        __syncthreads();
    }

    if (!SKEW) {
#pragma unroll
        for (int i = 0; i < 8; i++) {
            float* cp = C + (size_t)(bm + ty * 8 + i) * N + bn + tx * 8;
            *reinterpret_cast<float4*>(cp)     = make_float4(acc[i][0], acc[i][1], acc[i][2], acc[i][3]);
            *reinterpret_cast<float4*>(cp + 4) = make_float4(acc[i][4], acc[i][5], acc[i][6], acc[i][7]);
        }
    } else {
        // Skew gather: Srel[l,m] = QE[l, m-l+L-1]        (m <= l)
        //              0                                  (m == l+1)
        //              QE[l+1, m-l-2]                     (m >= l+2)
        const float scale = 0.0625f;  // 1/sqrt(256)
        const int b = blockIdx.z;
#pragma unroll
        for (int i = 0; i < 8; i++) {
            const int l = bm + ty * 8 + i;
            const size_t row0 = (size_t)(b * L_ + l) * L_;
            const size_t row1 = (size_t)(b * L_ + l + 1) * L_;  // only read when valid
            float* cp = C + (size_t)l * N + bn + tx * 8;
#pragma unroll
            for (int j = 0; j < 8; j++) {
                const int m = bn + tx * 8 + j;
                float srel;
                if (m <= l)           srel = QE[row0 + (m - l + L_ - 1)];
                else if (m == l + 1)  srel = 0.f;
                else                  srel = QE[row1 + (m - l - 2)];
                cp[j] = (acc[i][j] + srel) * scale;
            }
        }
    }
}

// ---------------------------------------------------------------------------
// Row softmax over 2048 elements: one block per row, 256 threads x 8 elements.
// ---------------------------------------------------------------------------
__global__ void softmax2048(float* __restrict__ S)
{
    __shared__ float red[8];
    const size_t row = blockIdx.x;
    float* p = S + row * (size_t)L_;
    const int tid = threadIdx.x;

    float v[8];
    float mx = -1e30f;
#pragma unroll
    for (int i = 0; i < 8; i++) {
        v[i] = p[tid + i * 256];
        mx = fmaxf(mx, v[i]);
    }
#pragma unroll
    for (int o = 16; o > 0; o >>= 1)
        mx = fmaxf(mx, __shfl_xor_sync(0xffffffffu, mx, o));
    if ((tid & 31) == 0) red[tid >> 5] = mx;
    __syncthreads();
    mx = red[0];
#pragma unroll
    for (int w = 1; w < 8; w++) mx = fmaxf(mx, red[w]);
    __syncthreads();

    float sum = 0.f;
#pragma unroll
    for (int i = 0; i < 8; i++) {
        v[i] = __expf(v[i] - mx);
        sum += v[i];
    }
#pragma unroll
    for (int o = 16; o > 0; o >>= 1)
        sum += __shfl_xor_sync(0xffffffffu, sum, o);
    if ((tid & 31) == 0) red[tid >> 5] = sum;
    __syncthreads();
    float tot = 0.f;
#pragma unroll
    for (int w = 0; w < 8; w++) tot += red[w];

    const float inv = 1.f / tot;
#pragma unroll
    for (int i = 0; i < 8; i++) p[tid + i * 256] = v[i] * inv;
}

// ---------------------------------------------------------------------------
extern "C" void kernel_launch(void* const* d_in, const int* in_sizes, int n_in,
                              void* d_out, int out_size)
{
    const float* inQ = (const float*)d_in[0];
    const float* inK = (const float*)d_in[1];
    const float* inV = (const float*)d_in[2];
    const float* Wq  = (const float*)d_in[3];
    const float* Wk  = (const float*)d_in[4];
    const float* Wv  = (const float*)d_in[5];
    const float* E   = (const float*)d_in[6];
    float* out = (float*)d_out;

    float *Q, *K, *V, *QE, *S;
    cudaGetSymbolAddress((void**)&Q,  g_Q);
    cudaGetSymbolAddress((void**)&K,  g_K);
    cudaGetSymbolAddress((void**)&V,  g_V);
    cudaGetSymbolAddress((void**)&QE, g_QE);
    cudaGetSymbolAddress((void**)&S,  g_S);

    const int BL = B_ * L_;  // 8192

    // Projections: [8192,512] x [512,{256,256,512}]
    sgemm_nn<<<dim3(DK_ / 128, BL / 128, 1), 256>>>(inQ, Wq, Q, BL, DK_, D_, 0, 0, 0);
    sgemm_nn<<<dim3(DK_ / 128, BL / 128, 1), 256>>>(inK, Wk, K, BL, DK_, D_, 0, 0, 0);
    sgemm_nn<<<dim3(D_  / 128, BL / 128, 1), 256>>>(inV, Wv, V, BL, D_,  D_, 0, 0, 0);

    // QE = Q * E^T : [8192,256] x [2048,256]^T -> [8192,2048]
    sgemm_nt<false><<<dim3(L_ / 128, BL / 128, 1), 256>>>(
        Q, E, QE, BL, L_, DK_, 0, 0, 0, nullptr);

    // S = (Q K^T + skew(QE)) / 16, batched over B
    sgemm_nt<true><<<dim3(L_ / 128, L_ / 128, B_), 256>>>(
        Q, K, S, L_, L_, DK_,
        (long long)L_ * DK_, (long long)L_ * DK_, (long long)L_ * L_, QE);

    // softmax along rows
    softmax2048<<<BL, 256>>>(S);

    // out = P * V, batched over B: [2048,2048] x [2048,512]
    sgemm_nn<<<dim3(D_ / 128, L_ / 128, B_), 256>>>(
        S, V, out, L_, D_, L_,
        (long long)L_ * L_, (long long)L_ * D_, (long long)L_ * D_);
}

// round 4
// speedup vs baseline: 2.8469x; 2.8469x over previous
#include <cuda_runtime.h>
#include <cstdint>

#define B_  4
#define L_  2048
#define D_  512
#define DK_ 256

// Scratch (allocation-free per harness rules)
__device__ float g_Q[B_ * L_ * DK_];
__device__ float g_K[B_ * L_ * DK_];
__device__ float g_V[B_ * L_ * D_];
__device__ float g_QE[(size_t)B_ * L_ * L_];
__device__ float g_S[(size_t)B_ * L_ * L_];

__device__ __forceinline__ uint32_t cvt_tf32(float x) {
    uint32_t r;
    asm("cvt.rna.tf32.f32 %0, %1;" : "=r"(r) : "f"(x));
    return r;
}

__device__ __forceinline__ uint4 cvt4(float4 v) {
    return make_uint4(cvt_tf32(v.x), cvt_tf32(v.y), cvt_tf32(v.z), cvt_tf32(v.w));
}

__device__ __forceinline__ void mma_tf32(float c[4], const uint32_t a[4], const uint32_t b[2]) {
    asm volatile(
        "mma.sync.aligned.m16n8k8.row.col.f32.tf32.tf32.f32 "
        "{%0,%1,%2,%3},{%4,%5,%6,%7},{%8,%9},{%0,%1,%2,%3};"
        : "+f"(c[0]), "+f"(c[1]), "+f"(c[2]), "+f"(c[3])
        : "r"(a[0]), "r"(a[1]), "r"(a[2]), "r"(a[3]), "r"(b[0]), "r"(b[1]));
}

// ---------------------------------------------------------------------------
// TF32 tensor-core GEMM. Block tile 128x128, K-chunk 32, 256 threads = 8 warps
// (2x4 warp grid, warp tile 64x32). fp32 accumulate.
//   TRANS_B=false: C = A[M,K] * B[K,N]           (row-major B)
//   TRANS_B=true : C = A[M,K] * B[N,K]^T
//   SKEW=true    : C = (A*B^T + skew(QE)) * 1/16 (QK^T epilogue)
// All dims divide tiles exactly; no predication.
// ---------------------------------------------------------------------------
template <bool TRANS_B, bool SKEW>
__global__ __launch_bounds__(256)
void tgemm(const float* __restrict__ A, const float* __restrict__ Bm,
           float* __restrict__ C, int M, int N, int Kd,
           long long sA, long long sB, long long sC,
           const float* __restrict__ QE)
{
    // A tile: [m 0..127][k 0..31], stride 36 words  (frag-load bank == lane)
    __shared__ uint32_t As[128 * 36];
    // B tile: NT -> [n][k] stride 36; NN -> [k][n] stride 136
    __shared__ uint32_t Bs[TRANS_B ? (128 * 36) : (32 * 136)];

    const int bz = blockIdx.z;
    A  += (size_t)bz * sA;
    Bm += (size_t)bz * sB;
    C  += (size_t)bz * sC;

    const int bm = blockIdx.y * 128;
    const int bn = blockIdx.x * 128;
    const int tid  = threadIdx.x;
    const int lane = tid & 31;
    const int warp = tid >> 5;
    const int wm = warp & 1;   // 0..1  (64-row slab)
    const int wn = warp >> 1;  // 0..3  (32-col slab)

    // global-load mapping: 128x32-float tile, 4 float4 per thread
    const int arow  = tid >> 3;          // 0..31
    const int acol4 = (tid & 7) << 2;    // 0,4,..28
    // NN B tile: 32x128 floats
    const int brow  = tid >> 5;          // 0..7
    const int bcol4 = (tid & 31) << 2;   // 0..124

    float acc[4][4][4];
#pragma unroll
    for (int i = 0; i < 4; i++)
#pragma unroll
        for (int j = 0; j < 4; j++)
#pragma unroll
            for (int e = 0; e < 4; e++) acc[i][j][e] = 0.f;

    float4 ra[4], rb[4];

    // prologue load k0 = 0
#pragma unroll
    for (int i = 0; i < 4; i++)
        ra[i] = *reinterpret_cast<const float4*>(
            A + (size_t)(bm + arow + 32 * i) * Kd + acol4);
#pragma unroll
    for (int i = 0; i < 4; i++) {
        if (TRANS_B)
            rb[i] = *reinterpret_cast<const float4*>(
                Bm + (size_t)(bn + arow + 32 * i) * Kd + acol4);
        else
            rb[i] = *reinterpret_cast<const float4*>(
                Bm + (size_t)(brow + 8 * i) * N + bn + bcol4);
    }

    for (int k0 = 0; k0 < Kd; k0 += 32) {
#pragma unroll
        for (int i = 0; i < 4; i++)
            *reinterpret_cast<uint4*>(&As[(arow + 32 * i) * 36 + acol4]) = cvt4(ra[i]);
#pragma unroll
        for (int i = 0; i < 4; i++) {
            if (TRANS_B)
                *reinterpret_cast<uint4*>(&Bs[(arow + 32 * i) * 36 + acol4]) = cvt4(rb[i]);
            else
                *reinterpret_cast<uint4*>(&Bs[(brow + 8 * i) * 136 + bcol4]) = cvt4(rb[i]);
        }
        __syncthreads();

        if (k0 + 32 < Kd) {
            const int kn = k0 + 32;
#pragma unroll
            for (int i = 0; i < 4; i++)
                ra[i] = *reinterpret_cast<const float4*>(
                    A + (size_t)(bm + arow + 32 * i) * Kd + kn + acol4);
#pragma unroll
            for (int i = 0; i < 4; i++) {
                if (TRANS_B)
                    rb[i] = *reinterpret_cast<const float4*>(
                        Bm + (size_t)(bn + arow + 32 * i) * Kd + kn + acol4);
                else
                    rb[i] = *reinterpret_cast<const float4*>(
                        Bm + (size_t)(kn + brow + 8 * i) * N + bn + bcol4);
            }
        }

#pragma unroll
        for (int kb = 0; kb < 4; kb++) {
            const int kk = kb * 8;
            uint32_t af[4][4];
#pragma unroll
            for (int mi = 0; mi < 4; mi++) {
                const int m = wm * 64 + mi * 16 + (lane >> 2);
                const int kc = kk + (lane & 3);
                af[mi][0] = As[m * 36 + kc];
                af[mi][1] = As[(m + 8) * 36 + kc];
                af[mi][2] = As[m * 36 + kc + 4];
                af[mi][3] = As[(m + 8) * 36 + kc + 4];
            }
            uint32_t bf[4][2];
#pragma unroll
            for (int ni = 0; ni < 4; ni++) {
                const int n = wn * 32 + ni * 8 + (lane >> 2);
                if (TRANS_B) {
                    bf[ni][0] = Bs[n * 36 + kk + (lane & 3)];
                    bf[ni][1] = Bs[n * 36 + kk + 4 + (lane & 3)];
                } else {
                    bf[ni][0] = Bs[(kk + (lane & 3)) * 136 + n];
                    bf[ni][1] = Bs[(kk + 4 + (lane & 3)) * 136 + n];
                }
            }
#pragma unroll
            for (int mi = 0; mi < 4; mi++)
#pragma unroll
                for (int ni = 0; ni < 4; ni++)
                    mma_tf32(acc[mi][ni], af[mi], bf[ni]);
        }
        __syncthreads();
    }

    // epilogue
    if (!SKEW) {
#pragma unroll
        for (int mi = 0; mi < 4; mi++) {
            const int r0 = bm + wm * 64 + mi * 16 + (lane >> 2);
#pragma unroll
            for (int ni = 0; ni < 4; ni++) {
                const int c0 = bn + wn * 32 + ni * 8 + 2 * (lane & 3);
                *reinterpret_cast<float2*>(C + (size_t)r0 * N + c0) =
                    make_float2(acc[mi][ni][0], acc[mi][ni][1]);
                *reinterpret_cast<float2*>(C + (size_t)(r0 + 8) * N + c0) =
                    make_float2(acc[mi][ni][2], acc[mi][ni][3]);
            }
        }
    } else {
        // Srel[l,m] = QE[l, m-l+L-1]   (m <= l)
        //           = 0                 (m == l+1)
        //           = QE[l+1, m-l-2]    (m >= l+2)
        const float scale = 0.0625f;  // 1/sqrt(256)
        const int b = blockIdx.z;
#pragma unroll
        for (int mi = 0; mi < 4; mi++) {
            const int rbase = bm + wm * 64 + mi * 16 + (lane >> 2);
#pragma unroll
            for (int ni = 0; ni < 4; ni++) {
                const int c0 = bn + wn * 32 + ni * 8 + 2 * (lane & 3);
#pragma unroll
                for (int h = 0; h < 2; h++) {
                    const int l = rbase + 8 * h;
                    const size_t row0 = (size_t)(b * L_ + l) * L_;
                    const size_t row1 = (size_t)(b * L_ + l + 1) * L_;
                    float out[2];
#pragma unroll
                    for (int e = 0; e < 2; e++) {
                        const int m = c0 + e;
                        float srel;
                        if (m <= l)          srel = QE[row0 + (m - l + L_ - 1)];
                        else if (m == l + 1) srel = 0.f;
                        else                 srel = QE[row1 + (m - l - 2)];
                        out[e] = (acc[mi][ni][2 * h + e] + srel) * scale;
                    }
                    *reinterpret_cast<float2*>(C + (size_t)l * N + c0) =
                        make_float2(out[0], out[1]);
                }
            }
        }
    }
}

// ---------------------------------------------------------------------------
// Row softmax over 2048 elements: one block per row, 256 threads x 8 elements.
// ---------------------------------------------------------------------------
__global__ void softmax2048(float* __restrict__ S)
{
    __shared__ float red[8];
    const size_t row = blockIdx.x;
    float* p = S + row * (size_t)L_;
    const int tid = threadIdx.x;

    float v[8];
    float mx = -1e30f;
#pragma unroll
    for (int i = 0; i < 8; i++) {
        v[i] = p[tid + i * 256];
        mx = fmaxf(mx, v[i]);
    }
#pragma unroll
    for (int o = 16; o > 0; o >>= 1)
        mx = fmaxf(mx, __shfl_xor_sync(0xffffffffu, mx, o));
    if ((tid & 31) == 0) red[tid >> 5] = mx;
    __syncthreads();
    mx = red[0];
#pragma unroll
    for (int w = 1; w < 8; w++) mx = fmaxf(mx, red[w]);
    __syncthreads();

    float sum = 0.f;
#pragma unroll
    for (int i = 0; i < 8; i++) {
        v[i] = __expf(v[i] - mx);
        sum += v[i];
    }
#pragma unroll
    for (int o = 16; o > 0; o >>= 1)
        sum += __shfl_xor_sync(0xffffffffu, sum, o);
    if ((tid & 31) == 0) red[tid >> 5] = sum;
    __syncthreads();
    float tot = 0.f;
#pragma unroll
    for (int w = 0; w < 8; w++) tot += red[w];

    const float inv = 1.f / tot;
#pragma unroll
    for (int i = 0; i < 8; i++) p[tid + i * 256] = v[i] * inv;
}

// ---------------------------------------------------------------------------
extern "C" void kernel_launch(void* const* d_in, const int* in_sizes, int n_in,
                              void* d_out, int out_size)
{
    const float* inQ = (const float*)d_in[0];
    const float* inK = (const float*)d_in[1];
    const float* inV = (const float*)d_in[2];
    const float* Wq  = (const float*)d_in[3];
    const float* Wk  = (const float*)d_in[4];
    const float* Wv  = (const float*)d_in[5];
    const float* E   = (const float*)d_in[6];
    float* out = (float*)d_out;

    float *Q, *K, *V, *QE, *S;
    cudaGetSymbolAddress((void**)&Q,  g_Q);
    cudaGetSymbolAddress((void**)&K,  g_K);
    cudaGetSymbolAddress((void**)&V,  g_V);
    cudaGetSymbolAddress((void**)&QE, g_QE);
    cudaGetSymbolAddress((void**)&S,  g_S);

    const int BL = B_ * L_;  // 8192

    // Projections: [8192,512] x [512,{256,256,512}] (NN)
    tgemm<false, false><<<dim3(DK_ / 128, BL / 128, 1), 256>>>(
        inQ, Wq, Q, BL, DK_, D_, 0, 0, 0, nullptr);
    tgemm<false, false><<<dim3(DK_ / 128, BL / 128, 1), 256>>>(
        inK, Wk, K, BL, DK_, D_, 0, 0, 0, nullptr);
    tgemm<false, false><<<dim3(D_ / 128, BL / 128, 1), 256>>>(
        inV, Wv, V, BL, D_, D_, 0, 0, 0, nullptr);

    // QE = Q * E^T : [8192,256] x [2048,256]^T -> [8192,2048] (NT)
    tgemm<true, false><<<dim3(L_ / 128, BL / 128, 1), 256>>>(
        Q, E, QE, BL, L_, DK_, 0, 0, 0, nullptr);

    // S = (Q K^T + skew(QE)) / 16, batched over B (NT + skew epilogue)
    tgemm<true, true><<<dim3(L_ / 128, L_ / 128, B_), 256>>>(
        Q, K, S, L_, L_, DK_,
        (long long)L_ * DK_, (long long)L_ * DK_, (long long)L_ * L_, QE);

    // softmax along rows
    softmax2048<<<BL, 256>>>(S);

    // out = P * V, batched over B: [2048,2048] x [2048,512] (NN)
    tgemm<false, false><<<dim3(D_ / 128, L_ / 128, B_), 256>>>(
        S, V, out, L_, D_, L_,
        (long long)L_ * L_, (long long)L_ * D_, (long long)L_ * D_, nullptr);
}